// round 2
// baseline (speedup 1.0000x reference)
#include <cuda_runtime.h>
#include <cuda_bf16.h>
#include <cstdint>

// AtomicComposition: counts[s][k] = #atoms in structure s with species == all_species[k]
// species:            d_in[2]  int32  [n_atoms]
// structure_offsets:  d_in[8]  int32 OR int64 [n_structures] (CSR starts) -- dtype probed on device
// all_species:        d_in[9]  int32  [n_species]
// out: float32 [n_structures, n_species]

__device__ __forceinline__ long long load_offset(const void* offs, int i, bool is64) {
    if (is64) return ((const long long*)offs)[i];
    return (long long)((const int*)offs)[i];
}

template <int NS>
__global__ __launch_bounds__(64) void atomic_composition_kernel(
    const int* __restrict__ species,
    const void* __restrict__ offsets,
    const int* __restrict__ all_species,
    float* __restrict__ out,
    int n_structures,
    long long n_atoms)
{
    const int s   = blockIdx.x;
    const int tid = threadIdx.x;           // 64 threads, 2 warps
    const int wid = tid >> 5;
    const int lid = tid & 31;

    // dtype probe: if offsets are genuine int64, element [1] is a small valid
    // offset; if they are int32 misread as int64, it's (a[2] | a[3]<<32), huge.
    bool is64 = true;
    if (n_structures > 1) {
        const long long probe = ((const long long*)offsets)[1];
        is64 = (probe >= 0 && probe <= n_atoms);
    }

    const long long start = load_offset(offsets, s, is64);
    const long long end   = (s + 1 < n_structures) ? load_offset(offsets, s + 1, is64)
                                                   : n_atoms;

    // species values in registers
    int sp[NS];
#pragma unroll
    for (int k = 0; k < NS; ++k) sp[k] = __ldg(&all_species[k]);

    int cnt[NS];
#pragma unroll
    for (int k = 0; k < NS; ++k) cnt[k] = 0;

    if ((start & 3LL) == 0) {
        // fast path: vectorized int4 loads, fully coalesced
        const long long nquads = (end - start) >> 2;   // full quads
        for (long long q = tid; q < nquads; q += 64) {
            const int4 v = *reinterpret_cast<const int4*>(species + start + (q << 2));
#pragma unroll
            for (int k = 0; k < NS; ++k) {
                cnt[k] += (v.x == sp[k]) + (v.y == sp[k]) + (v.z == sp[k]) + (v.w == sp[k]);
            }
        }
        // tail (0-3 elements)
        for (long long j = start + (nquads << 2) + tid; j < end; j += 64) {
            const int z = species[j];
#pragma unroll
            for (int k = 0; k < NS; ++k) cnt[k] += (z == sp[k]);
        }
    } else {
        // generic scalar path (unaligned start)
        for (long long j = start + tid; j < end; j += 64) {
            const int z = species[j];
#pragma unroll
            for (int k = 0; k < NS; ++k) cnt[k] += (z == sp[k]);
        }
    }

    // warp reduction
#pragma unroll
    for (int k = 0; k < NS; ++k) cnt[k] = __reduce_add_sync(0xFFFFFFFFu, cnt[k]);

    __shared__ int sh[2][NS];
    if (lid == 0) {
#pragma unroll
        for (int k = 0; k < NS; ++k) sh[wid][k] = cnt[k];
    }
    __syncthreads();

    if (tid < NS) {
        out[(long long)s * NS + tid] = (float)(sh[0][tid] + sh[1][tid]);
    }
}

// Fallback for arbitrary n_species (shared-memory counters)
__global__ __launch_bounds__(64) void atomic_composition_generic(
    const int* __restrict__ species,
    const void* __restrict__ offsets,
    const int* __restrict__ all_species,
    float* __restrict__ out,
    int n_structures,
    long long n_atoms,
    int n_species)
{
    extern __shared__ int shc[];
    const int s   = blockIdx.x;
    const int tid = threadIdx.x;
    for (int k = tid; k < n_species; k += 64) shc[k] = 0;
    __syncthreads();

    bool is64 = true;
    if (n_structures > 1) {
        const long long probe = ((const long long*)offsets)[1];
        is64 = (probe >= 0 && probe <= n_atoms);
    }

    const long long start = load_offset(offsets, s, is64);
    const long long end   = (s + 1 < n_structures) ? load_offset(offsets, s + 1, is64)
                                                   : n_atoms;
    for (long long j = start + tid; j < end; j += 64) {
        const int z = species[j];
        for (int k = 0; k < n_species; ++k)
            if (z == __ldg(&all_species[k])) atomicAdd(&shc[k], 1);
    }
    __syncthreads();
    for (int k = tid; k < n_species; k += 64)
        out[(long long)s * n_species + k] = (float)shc[k];
}

extern "C" void kernel_launch(void* const* d_in, const int* in_sizes, int n_in,
                              void* d_out, int out_size)
{
    const int*  species     = (const int*)d_in[2];
    const void* offsets     = d_in[8];
    const int*  all_species = (const int*)d_in[9];
    float*      out         = (float*)d_out;

    const long long n_atoms      = (long long)in_sizes[2];
    const int       n_structures = in_sizes[8];
    const int       n_species    = in_sizes[9];

    if (n_species == 5) {
        atomic_composition_kernel<5><<<n_structures, 64>>>(
            species, offsets, all_species, out, n_structures, n_atoms);
    } else {
        atomic_composition_generic<<<n_structures, 64, n_species * sizeof(int)>>>(
            species, offsets, all_species, out, n_structures, n_atoms, n_species);
    }
}

// round 4
// speedup vs baseline: 1.8020x; 1.8020x over previous
#include <cuda_runtime.h>
#include <cuda_bf16.h>
#include <cstdint>

// AtomicComposition: counts[s][k] = #atoms in structure s with species == all_species[k]
// species:            d_in[2]  int32  [n_atoms]
// structure_offsets:  d_in[8]  int32 OR int64 [n_structures] (CSR starts) -- dtype probed on device
// all_species:        d_in[9]  int32  [n_species]
// out: float32 [n_structures, n_species]

__device__ __forceinline__ long long load_offset(const void* offs, int i, bool is64) {
    if (is64) return ((const long long*)offs)[i];
    return (long long)((const int*)offs)[i];
}

__device__ __forceinline__ bool probe_is64(const void* offs, int n_structures,
                                           long long n_atoms) {
    // If offsets are genuine int64, element [1] is a small valid offset.
    // If int32 data is misread as int64, it becomes (a[2] | a[3]<<32): huge.
    if (n_structures <= 1) return true;
    const long long probe = ((const long long*)offs)[1];
    return (probe >= 0 && probe <= n_atoms);
}

// One warp per structure. 256 threads = 8 warps per CTA.
template <int NS>
__global__ __launch_bounds__(256) void atomic_composition_warp(
    const int* __restrict__ species,
    const void* __restrict__ offsets,
    const int* __restrict__ all_species,
    float* __restrict__ out,
    int n_structures,
    long long n_atoms)
{
    const int gwarp = (blockIdx.x * blockDim.x + threadIdx.x) >> 5;
    const int lid   = threadIdx.x & 31;
    if (gwarp >= n_structures) return;
    const int s = gwarp;

    const bool is64 = probe_is64(offsets, n_structures, n_atoms);

    const long long start = load_offset(offsets, s, is64);
    const long long end   = (s + 1 < n_structures) ? load_offset(offsets, s + 1, is64)
                                                   : n_atoms;

    int sp[NS];
#pragma unroll
    for (int k = 0; k < NS; ++k) sp[k] = __ldg(&all_species[k]);

    int cnt[NS];
#pragma unroll
    for (int k = 0; k < NS; ++k) cnt[k] = 0;

    const long long n = end - start;

    if (((start & 3LL) == 0) && n > 0) {
        const int4* __restrict__ base = reinterpret_cast<const int4*>(species + start);
        const long long nq = n >> 2;          // full int4 quads
        long long q = lid;
        // MLP=2: two independent LDG.128 in flight per thread.
        for (; q + 32 < nq; q += 64) {
            const int4 a = base[q];
            const int4 b = base[q + 32];
#pragma unroll
            for (int k = 0; k < NS; ++k) {
                cnt[k] += (a.x == sp[k]) + (a.y == sp[k]) + (a.z == sp[k]) + (a.w == sp[k]);
                cnt[k] += (b.x == sp[k]) + (b.y == sp[k]) + (b.z == sp[k]) + (b.w == sp[k]);
            }
        }
        for (; q < nq; q += 32) {
            const int4 a = base[q];
#pragma unroll
            for (int k = 0; k < NS; ++k) {
                cnt[k] += (a.x == sp[k]) + (a.y == sp[k]) + (a.z == sp[k]) + (a.w == sp[k]);
            }
        }
        // scalar tail (0-3 atoms)
        for (long long j = start + (nq << 2) + lid; j < end; j += 32) {
            const int z = species[j];
#pragma unroll
            for (int k = 0; k < NS; ++k) cnt[k] += (z == sp[k]);
        }
    } else {
        for (long long j = start + lid; j < end; j += 32) {
            const int z = species[j];
#pragma unroll
            for (int k = 0; k < NS; ++k) cnt[k] += (z == sp[k]);
        }
    }

#pragma unroll
    for (int k = 0; k < NS; ++k) cnt[k] = __reduce_add_sync(0xFFFFFFFFu, cnt[k]);

    if (lid == 0) {
        float* o = out + (long long)s * NS;
#pragma unroll
        for (int k = 0; k < NS; ++k) o[k] = (float)cnt[k];
    }
}

// Fallback for arbitrary n_species (shared-memory counters, CTA per structure)
__global__ __launch_bounds__(64) void atomic_composition_generic(
    const int* __restrict__ species,
    const void* __restrict__ offsets,
    const int* __restrict__ all_species,
    float* __restrict__ out,
    int n_structures,
    long long n_atoms,
    int n_species)
{
    extern __shared__ int shc[];
    const int s   = blockIdx.x;
    const int tid = threadIdx.x;
    for (int k = tid; k < n_species; k += 64) shc[k] = 0;
    __syncthreads();

    const bool is64 = probe_is64(offsets, n_structures, n_atoms);
    const long long start = load_offset(offsets, s, is64);
    const long long end   = (s + 1 < n_structures) ? load_offset(offsets, s + 1, is64)
                                                   : n_atoms;
    for (long long j = start + tid; j < end; j += 64) {
        const int z = species[j];
        for (int k = 0; k < n_species; ++k)
            if (z == __ldg(&all_species[k])) atomicAdd(&shc[k], 1);
    }
    __syncthreads();
    for (int k = tid; k < n_species; k += 64)
        out[(long long)s * n_species + k] = (float)shc[k];
}

extern "C" void kernel_launch(void* const* d_in, const int* in_sizes, int n_in,
                              void* d_out, int out_size)
{
    const int*  species     = (const int*)d_in[2];
    const void* offsets     = d_in[8];
    const int*  all_species = (const int*)d_in[9];
    float*      out         = (float*)d_out;

    const long long n_atoms      = (long long)in_sizes[2];
    const int       n_structures = in_sizes[8];
    const int       n_species    = in_sizes[9];

    if (n_species == 5) {
        const int warps_per_cta = 8;                 // 256 threads
        const int ctas = (n_structures + warps_per_cta - 1) / warps_per_cta;
        atomic_composition_warp<5><<<ctas, 256>>>(
            species, offsets, all_species, out, n_structures, n_atoms);
    } else {
        atomic_composition_generic<<<n_structures, 64, n_species * sizeof(int)>>>(
            species, offsets, all_species, out, n_structures, n_atoms, n_species);
    }
}